// round 4
// baseline (speedup 1.0000x reference)
#include <cuda_runtime.h>
#include <cstdint>

// ============================================================================
// GCN layer on sm_103 (no tcgen05 in this toolchain -> mma.sync tf32 HMMA)
//   out = (D^-1/2 (A+I) D^-1/2) X W^T + b ;  B=8, N=2048, F=128, fp32.
// Pipeline:
//   K1 deg   : d[b,n] = rsqrt(sum_m adj[b,n,m] + 1)
//   K2 xsT   : xsT[b,f,m] = d[b,m] * x[b,m,f]           (K-major B operand)
//   K3 gemm0 : out1[n,f] = d_n * (sum_m adj[n,m]*xsT[f,m]) + d_n^2 * x[n,f]
//   K4 gemm1 : out[r,o]  = sum_f out1[r,f]*W[o,f] + bias[o]
// GEMM: tf32 mma.sync m16n8k8, CTA 128x128, 4 warps (64x64 each),
//       k-chunk 32, 3-stage cp.async, SMEM pitch 36 floats (conflict-free).
// All MMA operands pass through cvt.rna.tf32.f32 (unbiased rounding; raw
// truncation would give ~1e-3 coherent bias over K=2048 and fail 1e-3).
// ============================================================================

#define DINL __device__ __forceinline__

static const int BB = 8;
static const int NN = 2048;
static const int FF = 128;

static const int NSTAGES = 3;
static const int PITCH = 36;                       // floats per smem row (144B)
static const int TILE_FLOATS = 128 * PITCH;        // one operand tile
static const int STAGE_FLOATS = 2 * TILE_FLOATS;   // A then B
static const int SMEM_TOTAL = NSTAGES * STAGE_FLOATS * 4;  // 110592 B

__device__ __align__(128) float g_d[BB * NN];
__device__ __align__(128) float g_xsT[(size_t)BB * FF * NN];   // [b][f][m]
__device__ __align__(128) float g_out1[(size_t)BB * NN * FF];  // [b][n][f]

// ---------------------------------------------------------------------------
DINL uint32_t smem_u32(const void* p) {
    uint32_t a;
    asm("{ .reg .u64 t; cvta.to.shared.u64 t, %1; cvt.u32.u64 %0, t; }"
        : "=r"(a) : "l"(p));
    return a;
}
DINL void cpasync16(uint32_t s, const void* g) {
    asm volatile("cp.async.cg.shared.global [%0], [%1], 16;"
                 :: "r"(s), "l"(g) : "memory");
}
DINL void cp_commit() { asm volatile("cp.async.commit_group;" ::: "memory"); }
template <int n> DINL void cp_wait() {
    asm volatile("cp.async.wait_group %0;" :: "n"(n) : "memory");
}
DINL uint32_t f2tf(float f) {
    uint32_t r;
    asm("cvt.rna.tf32.f32 %0, %1;" : "=r"(r) : "f"(f));
    return r;
}
DINL void mma_tf32(float* c, const uint32_t* a, const uint32_t* b) {
    asm volatile(
        "mma.sync.aligned.m16n8k8.row.col.f32.tf32.tf32.f32 "
        "{%0,%1,%2,%3}, {%4,%5,%6,%7}, {%8,%9}, {%0,%1,%2,%3};"
        : "+f"(c[0]), "+f"(c[1]), "+f"(c[2]), "+f"(c[3])
        : "r"(a[0]), "r"(a[1]), "r"(a[2]), "r"(a[3]), "r"(b[0]), "r"(b[1]));
}

// ---------------------------------------------------------------------------
// K1: d[row] = rsqrt(sum(adj_row) + 1)
// ---------------------------------------------------------------------------
__global__ void __launch_bounds__(256) deg_kernel(const float* __restrict__ adj,
                                                  float* __restrict__ dout) {
    int row = blockIdx.x;
    const float4* p = (const float4*)(adj + (size_t)row * NN);
    float s = 0.f;
#pragma unroll
    for (int i = 0; i < 2; i++) {
        float4 v = p[threadIdx.x + i * 256];
        s += v.x + v.y + v.z + v.w;
    }
#pragma unroll
    for (int o = 16; o > 0; o >>= 1) s += __shfl_down_sync(0xffffffffu, s, o);
    __shared__ float red[8];
    if ((threadIdx.x & 31) == 0) red[threadIdx.x >> 5] = s;
    __syncthreads();
    if (threadIdx.x == 0) {
        float t = 0.f;
#pragma unroll
        for (int i = 0; i < 8; i++) t += red[i];
        dout[row] = rsqrtf(t + 1.0f);
    }
}

// ---------------------------------------------------------------------------
// K2: xsT[b][f][m] = d[b][m] * x[b][m][f]
// ---------------------------------------------------------------------------
__global__ void __launch_bounds__(256) xsT_kernel(const float* __restrict__ x,
                                                  const float* __restrict__ dvec,
                                                  float* __restrict__ xsT) {
    __shared__ float t[32][33];
    int b = blockIdx.z;
    int n0 = blockIdx.x * 32;
    int f0 = blockIdx.y * 32;
    int tx = threadIdx.x, ty = threadIdx.y;
#pragma unroll
    for (int j = ty; j < 32; j += 8) {
        int n = n0 + j;
        t[j][tx] = x[((size_t)b * NN + n) * FF + f0 + tx] * dvec[b * NN + n];
    }
    __syncthreads();
#pragma unroll
    for (int j = ty; j < 32; j += 8) {
        xsT[(size_t)b * FF * NN + (size_t)(f0 + j) * NN + n0 + tx] = t[tx][j];
    }
}

// ---------------------------------------------------------------------------
// K3/K4: tf32 GEMM, C[128x128] per CTA.
//   C[r][c] = sum_k A[r][k] * Bt[c][k]    (Bt rows are output-cols, k-major)
// mode 0: A=adj tile, Bt=xsT(batch); epi: v = d_r*acc + d_r^2*x[r][c]
// mode 1: A=out1,     Bt=W;          epi: v = acc + bias[c]
// ---------------------------------------------------------------------------
DINL void load_stage(float* smem, int s, int k, const float* Ab, int lda,
                     const float* Bb, int ldb, int tid) {
    uint32_t base = smem_u32(smem) + (uint32_t)s * STAGE_FLOATS * 4;
#pragma unroll
    for (int i = 0; i < 8; i++) {
        int idx = tid + i * 128;             // 0..1023
        int row = idx >> 3, ch = idx & 7;
        const char* g = (const char*)Ab + (size_t)row * lda * 4 + (size_t)k * 128 + ch * 16;
        cpasync16(base + (uint32_t)row * 144 + ch * 16, g);
    }
    base += TILE_FLOATS * 4;
#pragma unroll
    for (int i = 0; i < 8; i++) {
        int idx = tid + i * 128;
        int row = idx >> 3, ch = idx & 7;
        const char* g = (const char*)Bb + (size_t)row * ldb * 4 + (size_t)k * 128 + ch * 16;
        cpasync16(base + (uint32_t)row * 144 + ch * 16, g);
    }
}

__global__ void __launch_bounds__(128, 1) gemm_tf32(
    const float* __restrict__ Ag, int lda,
    const float* __restrict__ Bg, int ldb,
    float* __restrict__ Og,
    int num_k, int mode,
    const float* __restrict__ dvec,
    const float* __restrict__ xg,
    const float* __restrict__ bias) {
    extern __shared__ float smem[];
    int tid = threadIdx.x;
    int wid = tid >> 5;
    int lane = tid & 31;
    int gid = lane >> 2, tg = lane & 3;
    int wm = wid >> 1, wn = wid & 1;  // warp grid 2x2, warp tile 64x64

    const float* Abase;
    const float* Bbase;
    float* Obase;
    const float* dvb = nullptr;
    const float* xb = nullptr;
    if (mode == 0) {
        int b = blockIdx.y;
        size_t row0 = (size_t)b * NN + blockIdx.x * 128;
        Abase = Ag + row0 * lda;
        Bbase = Bg + (size_t)b * FF * NN;
        Obase = Og + row0 * FF;
        dvb = dvec + row0;
        xb = xg + row0 * FF;
    } else {
        size_t row0 = (size_t)blockIdx.x * 128;
        Abase = Ag + row0 * lda;
        Bbase = Bg;
        Obase = Og + row0 * FF;
    }

    float C[4][8][4];
#pragma unroll
    for (int i = 0; i < 4; i++)
#pragma unroll
        for (int j = 0; j < 8; j++)
#pragma unroll
            for (int q = 0; q < 4; q++) C[i][j][q] = 0.f;

    // prologue: fill 2 stages
    load_stage(smem, 0, 0, Abase, lda, Bbase, ldb, tid);
    cp_commit();
    if (num_k > 1) load_stage(smem, 1, 1, Abase, lda, Bbase, ldb, tid);
    cp_commit();

    for (int k = 0; k < num_k; k++) {
        cp_wait<1>();
        __syncthreads();

        int nk = k + 2;
        if (nk < num_k)
            load_stage(smem, nk % NSTAGES, nk, Abase, lda, Bbase, ldb, tid);
        cp_commit();

        const float* As = smem + (k % NSTAGES) * STAGE_FLOATS;
        const float* Bs = As + TILE_FLOATS;
#pragma unroll
        for (int p = 0; p < 4; p++) {
            uint32_t a[4][4];
#pragma unroll
            for (int i = 0; i < 4; i++) {
                int r = wm * 64 + 16 * i + gid;
                int kc = 8 * p + tg;
                a[i][0] = f2tf(As[r * PITCH + kc]);
                a[i][1] = f2tf(As[(r + 8) * PITCH + kc]);
                a[i][2] = f2tf(As[r * PITCH + kc + 4]);
                a[i][3] = f2tf(As[(r + 8) * PITCH + kc + 4]);
            }
            uint32_t bq[8][2];
#pragma unroll
            for (int j = 0; j < 8; j++) {
                int n = wn * 64 + 8 * j + gid;
                int kc = 8 * p + tg;
                bq[j][0] = f2tf(Bs[n * PITCH + kc]);
                bq[j][1] = f2tf(Bs[n * PITCH + kc + 4]);
            }
#pragma unroll
            for (int i = 0; i < 4; i++)
#pragma unroll
                for (int j = 0; j < 8; j++) mma_tf32(C[i][j], a[i], bq[j]);
        }
        __syncthreads();
    }

    // epilogue: regs -> gmem (float2 stores)
#pragma unroll
    for (int i = 0; i < 4; i++) {
        int r = wm * 64 + 16 * i + gid;
        float d0 = 0.f, d1 = 0.f;
        if (mode == 0) { d0 = dvb[r]; d1 = dvb[r + 8]; }
#pragma unroll
        for (int j = 0; j < 8; j++) {
            int c = wn * 64 + 8 * j + 2 * tg;
            float v0 = C[i][j][0], v1 = C[i][j][1];
            float v2 = C[i][j][2], v3 = C[i][j][3];
            if (mode == 0) {
                v0 = d0 * v0 + d0 * d0 * xb[(size_t)r * FF + c];
                v1 = d0 * v1 + d0 * d0 * xb[(size_t)r * FF + c + 1];
                v2 = d1 * v2 + d1 * d1 * xb[(size_t)(r + 8) * FF + c];
                v3 = d1 * v3 + d1 * d1 * xb[(size_t)(r + 8) * FF + c + 1];
            } else {
                float b0 = bias[c], b1 = bias[c + 1];
                v0 += b0; v1 += b1; v2 += b0; v3 += b1;
            }
            *(float2*)(Obase + (size_t)r * FF + c) = make_float2(v0, v1);
            *(float2*)(Obase + (size_t)(r + 8) * FF + c) = make_float2(v2, v3);
        }
    }
}

// ---------------------------------------------------------------------------
extern "C" void kernel_launch(void* const* d_in, const int* in_sizes, int n_in,
                              void* d_out, int out_size) {
    (void)in_sizes; (void)n_in; (void)out_size;
    const float* x    = (const float*)d_in[0];  // [8,2048,128]
    const float* adj  = (const float*)d_in[1];  // [8,2048,2048]
    const float* W    = (const float*)d_in[2];  // [128,128]
    const float* bias = (const float*)d_in[3];  // [128]
    float* out = (float*)d_out;                 // [8,2048,128]

    float *dv, *xsT, *out1;
    cudaGetSymbolAddress((void**)&dv, g_d);
    cudaGetSymbolAddress((void**)&xsT, g_xsT);
    cudaGetSymbolAddress((void**)&out1, g_out1);

    cudaFuncSetAttribute(gemm_tf32, cudaFuncAttributeMaxDynamicSharedMemorySize,
                         SMEM_TOTAL);

    deg_kernel<<<BB * NN, 256>>>(adj, dv);
    xsT_kernel<<<dim3(NN / 32, FF / 32, BB), dim3(32, 8)>>>(x, dv, xsT);
    // aggregate GEMM: 16 M-tiles x 8 batches, K = 2048
    gemm_tf32<<<dim3(NN / 128, BB), 128, SMEM_TOTAL>>>(
        adj, NN, xsT, NN, out1, NN / 32, 0, dv, x, nullptr);
    // linear: [16384,128] @ W^T + bias, K = 128
    gemm_tf32<<<dim3(BB * NN / 128, 1), 128, SMEM_TOTAL>>>(
        out1, FF, W, FF, out, FF / 32, 1, nullptr, nullptr, bias);
}